// round 15
// baseline (speedup 1.0000x reference)
#include <cuda_runtime.h>
#include <cuda_fp16.h>
#include <cstdint>
#include <cstddef>

#define EXPERTS 8
#define TOK     2048
#define DMODEL  1024
#define HID     4096

// Static device scratch (no allocations allowed anywhere)
__device__ __half g_hidden[(size_t)EXPERTS * TOK * HID];   // fp16 hidden (written by k1)
__device__ __half g_x [(size_t)EXPERTS * TOK * DMODEL];    // fp16 x
__device__ __half g_w1[(size_t)EXPERTS * DMODEL * HID];    // fp16 w1
__device__ __half g_w2[(size_t)EXPERTS * HID * DMODEL];    // fp16 w2

// CTA tile 128x128, 128 threads (4 warps 2x2, 64x64 each), BK=32 fp16, 4-stage cp.async,
// 3 CTAs/SM. A via ldmatrix.x4 (pitch 80B odd-16B -> conflict-free),
// B via ldmatrix.x4.trans (pitch 272B odd-16B -> conflict-free).
// k2 uses SPLIT=2 (split-K) to fix its 2.31-wave tail; epilogue = red.global.add.f32
// onto a bias-prefilled output.
#define BM 128
#define BN 128
#define BK 32
#define APITCH 40      // halves (80 B/row)
#define BPITCH 136     // halves (272 B/row)
#define A_HALVES (BM * APITCH)            // 5120
#define B_HALVES (BK * BPITCH)            // 4352
#define S_HALVES (A_HALVES + B_HALVES)    // 9472 (18944 B/stage)
#define NSTAGE 4
#define DSMEM_BYTES (NSTAGE * S_HALVES * 2)   // 75776 B -> 3 CTAs/SM (222KB)

static __device__ __forceinline__ uint32_t smem_u32(const void* p) {
    uint32_t a;
    asm("{ .reg .u64 t; cvta.to.shared.u64 t, %1; cvt.u32.u64 %0, t; }" : "=r"(a) : "l"(p));
    return a;
}
static __device__ __forceinline__ void cp16(void* d, const void* s) {
    asm volatile("cp.async.cg.shared.global [%0], [%1], 16;" :: "r"(smem_u32(d)), "l"(s));
}
static __device__ __forceinline__ uint32_t h2u(__half2 h) {
    uint32_t u;
    asm("mov.b32 %0, %1;" : "=r"(u) : "r"(*(uint32_t*)&h));
    return u;
}
static __device__ __forceinline__ void red_f32(float* p, float v) {
    asm volatile("red.global.add.f32 [%0], %1;" :: "l"(p), "f"(v) : "memory");
}

// Merged fp32 -> fp16 prepass over three arrays, 8 floats/thread/iter
__global__ void to_half3(const float4* __restrict__ inx,  uint4* __restrict__ outx,  int nx8,
                         const float4* __restrict__ inw1, uint4* __restrict__ outw1, int nw18,
                         const float4* __restrict__ inw2, uint4* __restrict__ outw2, int nw28)
{
    const int total = nx8 + nw18 + nw28;
    for (int i = blockIdx.x * blockDim.x + threadIdx.x; i < total; i += gridDim.x * blockDim.x) {
        const float4* in;
        uint4* out;
        int k;
        if (i < nx8)             { in = inx;  out = outx;  k = i; }
        else if (i < nx8 + nw18) { in = inw1; out = outw1; k = i - nx8; }
        else                     { in = inw2; out = outw2; k = i - nx8 - nw18; }
        float4 v0 = in[2 * k];
        float4 v1 = in[2 * k + 1];
        __half2 h0 = __floats2half2_rn(v0.x, v0.y);
        __half2 h1 = __floats2half2_rn(v0.z, v0.w);
        __half2 h2 = __floats2half2_rn(v1.x, v1.y);
        __half2 h3 = __floats2half2_rn(v1.z, v1.w);
        uint4 o;
        o.x = h2u(h0); o.y = h2u(h1); o.z = h2u(h2); o.w = h2u(h3);
        out[k] = o;
    }
}

// Prefill out[e,t,:] = bias2[e,:] (float4 grid-stride). Quads/row = DMODEL/4.
__global__ void bias_bcast(const float4* __restrict__ b2, float4* __restrict__ out, int n4) {
    const int qrow = DMODEL / 4;                 // 256
    const int qexp = TOK * qrow;                 // quads per expert
    for (int i = blockIdx.x * blockDim.x + threadIdx.x; i < n4; i += gridDim.x * blockDim.x) {
        int e  = i / qexp;
        int dq = i % qrow;
        out[i] = b2[e * qrow + dq];
    }
}

// C = A[M,K]*B[K,N] (+bias).  A,B fp16 row-major.
// FIRST: +bias, ReLU, fp16 store (hidden). SPLIT==2: partial-K, red.add onto
// bias-prefilled fp32 out. Otherwise fp32 store +bias.
template <bool FIRST, int SPLIT>
__global__ __launch_bounds__(128, 3)
void ffn_gemm(const __half* __restrict__ A, const __half* __restrict__ B,
              const float* __restrict__ bias, void* __restrict__ Cv,
              int M, int N, int K)
{
    extern __shared__ __align__(16) __half sm[];

    const int e    = (SPLIT == 2) ? (blockIdx.z >> 1) : blockIdx.z;
    const int koff = (SPLIT == 2) ? (int)(blockIdx.z & 1) * (K / 2) : 0;
    const __half* Ae = A + (size_t)e * M * K + koff;
    const __half* Be = B + ((size_t)e * K + koff) * N;
    const float*  be = bias + (size_t)e * N;

    const int bm = blockIdx.y * BM;
    const int bn = blockIdx.x * BN;

    const int tid  = threadIdx.x;
    const int warp = tid >> 5;
    const int lane = tid & 31;
    const int wm   = (warp >> 1) * 64;
    const int wn   = (warp & 1) * 64;
    const int grp  = lane >> 2;
    const int qid  = lane & 3;
    const int rowsel = ((lane >> 3) & 1) * 8 + (lane & 7);  // row within 16
    const int col8   = (lane >> 4) * 8;                     // 8-half column block

    float c[4][8][4];
    #pragma unroll
    for (int i = 0; i < 4; i++)
        #pragma unroll
        for (int j = 0; j < 8; j++)
            #pragma unroll
            for (int r = 0; r < 4; r++) c[i][j][r] = 0.f;

    const int nk = K / (BK * SPLIT);

    // cp.async halves: A chunks, then B chunks; one commit per k-tile.
    auto issueA = [&](int t) {
        __half* As = sm + (t % NSTAGE) * S_HALVES;
        const int k0 = t * BK;
        #pragma unroll
        for (int i = 0; i < 4; i++) {
            int f = tid + (i << 7);
            int r = f >> 2, ch = (f & 3) << 3;
            cp16(As + r * APITCH + ch, Ae + (size_t)(bm + r) * K + k0 + ch);
        }
    };
    auto issueB = [&](int t) {
        __half* Bs = sm + (t % NSTAGE) * S_HALVES + A_HALVES;
        const int k0 = t * BK;
        #pragma unroll
        for (int i = 0; i < 4; i++) {
            int f = tid + (i << 7);
            int r = f >> 4, ch = (f & 15) << 3;
            cp16(Bs + r * BPITCH + ch, Be + (size_t)(k0 + r) * N + bn + ch);
        }
        asm volatile("cp.async.commit_group;" ::: "memory");
    };

    // Prologue: stages 0..2 in flight.
    issueA(0); issueB(0);
    issueA(1); issueB(1);
    issueA(2); issueB(2);

    for (int t = 0; t < nk; t++) {
        asm volatile("cp.async.wait_group 2;" ::: "memory");
        __syncthreads();

        const __half* As = sm + (t % NSTAGE) * S_HALVES;
        const __half* Bs = As + A_HALVES;
        const uint32_t abase = smem_u32(As) + (((wm + rowsel) * APITCH) + col8) * 2;
        const uint32_t bbase = smem_u32(Bs) + ((rowsel * BPITCH) + wn + col8) * 2;

        if (t + 3 < nk) issueA(t + 3);   // spread fill: A-half before ks0

        #pragma unroll
        for (int ks = 0; ks < 2; ks++) {
            uint32_t a[4][4];
            #pragma unroll
            for (int i = 0; i < 4; i++) {
                uint32_t addr = abase + (i * 16 * APITCH + ks * 16) * 2;
                asm volatile(
                    "ldmatrix.sync.aligned.m8n8.x4.shared.b16 {%0,%1,%2,%3}, [%4];"
                    : "=r"(a[i][0]), "=r"(a[i][1]), "=r"(a[i][2]), "=r"(a[i][3])
                    : "r"(addr));
            }
            #pragma unroll
            for (int jp = 0; jp < 4; jp++) {
                uint32_t b0, b1, b2, b3;   // n-tiles 2jp (b0,b1) and 2jp+1 (b2,b3)
                uint32_t addr = bbase + (ks * 16 * BPITCH + jp * 16) * 2;
                asm volatile(
                    "ldmatrix.sync.aligned.m8n8.x4.trans.shared.b16 {%0,%1,%2,%3}, [%4];"
                    : "=r"(b0), "=r"(b1), "=r"(b2), "=r"(b3)
                    : "r"(addr));
                #pragma unroll
                for (int i = 0; i < 4; i++) {
                    asm volatile(
                        "mma.sync.aligned.m16n8k16.row.col.f32.f16.f16.f32 "
                        "{%0,%1,%2,%3}, {%4,%5,%6,%7}, {%8,%9}, {%0,%1,%2,%3};"
                        : "+f"(c[i][2*jp][0]), "+f"(c[i][2*jp][1]),
                          "+f"(c[i][2*jp][2]), "+f"(c[i][2*jp][3])
                        : "r"(a[i][0]), "r"(a[i][1]), "r"(a[i][2]), "r"(a[i][3]),
                          "r"(b0), "r"(b1));
                    asm volatile(
                        "mma.sync.aligned.m16n8k16.row.col.f32.f16.f16.f32 "
                        "{%0,%1,%2,%3}, {%4,%5,%6,%7}, {%8,%9}, {%0,%1,%2,%3};"
                        : "+f"(c[i][2*jp+1][0]), "+f"(c[i][2*jp+1][1]),
                          "+f"(c[i][2*jp+1][2]), "+f"(c[i][2*jp+1][3])
                        : "r"(a[i][0]), "r"(a[i][1]), "r"(a[i][2]), "r"(a[i][3]),
                          "r"(b2), "r"(b3));
                }
            }
            if (ks == 0 && t + 3 < nk) issueB(t + 3);   // B-half + commit after ks0
        }
    }

    // Epilogue
    #pragma unroll
    for (int i = 0; i < 4; i++) {
        int r0 = bm + wm + i * 16 + grp;
        #pragma unroll
        for (int j = 0; j < 8; j++) {
            int cn = bn + wn + j * 8 + 2 * qid;
            if (FIRST) {
                float bv0 = be[cn], bv1 = be[cn + 1];
                __half* Ce = (__half*)Cv + (size_t)e * M * N;
                __half2 h01 = __floats2half2_rn(fmaxf(c[i][j][0] + bv0, 0.f),
                                                fmaxf(c[i][j][1] + bv1, 0.f));
                __half2 h23 = __floats2half2_rn(fmaxf(c[i][j][2] + bv0, 0.f),
                                                fmaxf(c[i][j][3] + bv1, 0.f));
                *(__half2*)&Ce[(size_t)r0 * N + cn]       = h01;
                *(__half2*)&Ce[(size_t)(r0 + 8) * N + cn] = h23;
            } else if (SPLIT == 2) {
                float* Ce = (float*)Cv + (size_t)e * M * N;
                red_f32(&Ce[(size_t)r0 * N + cn],           c[i][j][0]);
                red_f32(&Ce[(size_t)r0 * N + cn + 1],       c[i][j][1]);
                red_f32(&Ce[(size_t)(r0 + 8) * N + cn],     c[i][j][2]);
                red_f32(&Ce[(size_t)(r0 + 8) * N + cn + 1], c[i][j][3]);
            } else {
                float bv0 = be[cn], bv1 = be[cn + 1];
                float* Ce = (float*)Cv + (size_t)e * M * N;
                *(float2*)&Ce[(size_t)r0 * N + cn] =
                    make_float2(c[i][j][0] + bv0, c[i][j][1] + bv1);
                *(float2*)&Ce[(size_t)(r0 + 8) * N + cn] =
                    make_float2(c[i][j][2] + bv0, c[i][j][3] + bv1);
            }
        }
    }
}

extern "C" void kernel_launch(void* const* d_in, const int* in_sizes, int n_in,
                              void* d_out, int out_size)
{
    const float* x  = (const float*)d_in[0];   // [E, T, D]
    const float* w1 = (const float*)d_in[1];   // [E, D, H]
    const float* b1 = (const float*)d_in[2];   // [E, 1, H]
    const float* w2 = (const float*)d_in[3];   // [E, H, D]
    const float* b2 = (const float*)d_in[4];   // [E, 1, D]
    float* out = (float*)d_out;                // [E, T, D]

    __half *hid, *gx, *gw1, *gw2;
    cudaGetSymbolAddress((void**)&hid, g_hidden);
    cudaGetSymbolAddress((void**)&gx,  g_x);
    cudaGetSymbolAddress((void**)&gw1, g_w1);
    cudaGetSymbolAddress((void**)&gw2, g_w2);

    cudaFuncSetAttribute((const void*)ffn_gemm<true, 1>,
                         cudaFuncAttributeMaxDynamicSharedMemorySize, DSMEM_BYTES);
    cudaFuncSetAttribute((const void*)ffn_gemm<false, 2>,
                         cudaFuncAttributeMaxDynamicSharedMemorySize, DSMEM_BYTES);

    // Merged prepass: fp32 -> fp16 for x, w1, w2 in ONE launch
    const int nx8  = EXPERTS * TOK * DMODEL / 8;
    const int nw18 = EXPERTS * DMODEL * HID / 8;
    const int nw28 = EXPERTS * HID * DMODEL / 8;
    to_half3<<<1184, 256>>>((const float4*)x,  (uint4*)gx,  nx8,
                            (const float4*)w1, (uint4*)gw1, nw18,
                            (const float4*)w2, (uint4*)gw2, nw28);

    // Prefill out with broadcast bias2 (split-K halves RED onto it)
    bias_bcast<<<1184, 256>>>((const float4*)b2, (float4*)out,
                              EXPERTS * TOK * DMODEL / 4);

    dim3 blk(128);
    // k1: BM=128, grid 32x16x8 = 4096
    ffn_gemm<true, 1><<<dim3(HID / BN, TOK / BM, EXPERTS), blk, DSMEM_BYTES>>>(
        gx, gw1, b1, hid, TOK, HID, DMODEL);
    // k2: BM=128, split-K=2, grid 8x16x16 = 2048 (fixes 2.31-wave tail)
    ffn_gemm<false, 2><<<dim3(DMODEL / BN, TOK / BM, EXPERTS * 2), blk, DSMEM_BYTES>>>(
        hid, gw2, b2, out, TOK, DMODEL, HID);
}

// round 16
// speedup vs baseline: 1.0295x; 1.0295x over previous
#include <cuda_runtime.h>
#include <cuda_fp16.h>
#include <cstdint>
#include <cstddef>

#define EXPERTS 8
#define TOK     2048
#define DMODEL  1024
#define HID     4096

// Static device scratch (no allocations allowed anywhere)
__device__ __half g_hidden[(size_t)EXPERTS * TOK * HID];   // fp16 hidden (written by k1)
__device__ __half g_x [(size_t)EXPERTS * TOK * DMODEL];    // fp16 x
__device__ __half g_w1[(size_t)EXPERTS * DMODEL * HID];    // fp16 w1
__device__ __half g_w2[(size_t)EXPERTS * HID * DMODEL];    // fp16 w2

// CTA tile 128x128, 128 threads (4 warps 2x2, 64x64 each), BK=32 fp16, 4-stage cp.async,
// 3 CTAs/SM. A via ldmatrix.x4 (pitch 80B odd-16B -> conflict-free),
// B via ldmatrix.x4.trans (pitch 272B odd-16B -> conflict-free).
#define BM 128
#define BN 128
#define BK 32
#define APITCH 40      // halves (80 B/row)
#define BPITCH 136     // halves (272 B/row)
#define A_HALVES (BM * APITCH)            // 5120
#define B_HALVES (BK * BPITCH)            // 4352
#define S_HALVES (A_HALVES + B_HALVES)    // 9472 (18944 B/stage)
#define NSTAGE 4
#define DSMEM_BYTES (NSTAGE * S_HALVES * 2)   // 75776 B -> 3 CTAs/SM (222KB)

static __device__ __forceinline__ uint32_t smem_u32(const void* p) {
    uint32_t a;
    asm("{ .reg .u64 t; cvta.to.shared.u64 t, %1; cvt.u32.u64 %0, t; }" : "=r"(a) : "l"(p));
    return a;
}
static __device__ __forceinline__ void cp16(void* d, const void* s) {
    asm volatile("cp.async.cg.shared.global [%0], [%1], 16;" :: "r"(smem_u32(d)), "l"(s));
}
static __device__ __forceinline__ uint32_t h2u(__half2 h) {
    uint32_t u;
    asm("mov.b32 %0, %1;" : "=r"(u) : "r"(*(uint32_t*)&h));
    return u;
}
// streaming (evict-first) float2 store — for outputs that are never re-read
static __device__ __forceinline__ void st_cs_f2(float* p, float x, float y) {
    asm volatile("st.global.cs.v2.f32 [%0], {%1, %2};" :: "l"(p), "f"(x), "f"(y) : "memory");
}

// Merged fp32 -> fp16 prepass over three arrays, 8 floats/thread/iter
__global__ void to_half3(const float4* __restrict__ inx,  uint4* __restrict__ outx,  int nx8,
                         const float4* __restrict__ inw1, uint4* __restrict__ outw1, int nw18,
                         const float4* __restrict__ inw2, uint4* __restrict__ outw2, int nw28)
{
    const int total = nx8 + nw18 + nw28;
    for (int i = blockIdx.x * blockDim.x + threadIdx.x; i < total; i += gridDim.x * blockDim.x) {
        const float4* in;
        uint4* out;
        int k;
        if (i < nx8)             { in = inx;  out = outx;  k = i; }
        else if (i < nx8 + nw18) { in = inw1; out = outw1; k = i - nx8; }
        else                     { in = inw2; out = outw2; k = i - nx8 - nw18; }
        float4 v0 = in[2 * k];
        float4 v1 = in[2 * k + 1];
        __half2 h0 = __floats2half2_rn(v0.x, v0.y);
        __half2 h1 = __floats2half2_rn(v0.z, v0.w);
        __half2 h2 = __floats2half2_rn(v1.x, v1.y);
        __half2 h3 = __floats2half2_rn(v1.z, v1.w);
        uint4 o;
        o.x = h2u(h0); o.y = h2u(h1); o.z = h2u(h2); o.w = h2u(h3);
        out[k] = o;
    }
}

// C = A[M,K]*B[K,N] + bias.  A,B fp16 row-major.  FIRST: ReLU + fp16 store (hidden);
// else: fp32 streaming store. Batched over blockIdx.z.
template <bool FIRST>
__global__ __launch_bounds__(128, 3)
void ffn_gemm(const __half* __restrict__ A, const __half* __restrict__ B,
              const float* __restrict__ bias, void* __restrict__ Cv,
              int M, int N, int K)
{
    extern __shared__ __align__(16) __half sm[];

    const int e = blockIdx.z;
    const __half* Ae = A + (size_t)e * M * K;
    const __half* Be = B + (size_t)e * K * N;
    const float*  be = bias + (size_t)e * N;

    const int bm = blockIdx.y * BM;
    const int bn = blockIdx.x * BN;

    const int tid  = threadIdx.x;
    const int warp = tid >> 5;
    const int lane = tid & 31;
    const int wm   = (warp >> 1) * 64;
    const int wn   = (warp & 1) * 64;
    const int grp  = lane >> 2;
    const int qid  = lane & 3;
    const int rowsel = ((lane >> 3) & 1) * 8 + (lane & 7);  // row within 16
    const int col8   = (lane >> 4) * 8;                     // 8-half column block

    float c[4][8][4];
    #pragma unroll
    for (int i = 0; i < 4; i++)
        #pragma unroll
        for (int j = 0; j < 8; j++)
            #pragma unroll
            for (int r = 0; r < 4; r++) c[i][j][r] = 0.f;

    const int nk = K / BK;

    // cp.async halves: A chunks, then B chunks; one commit per k-tile.
    auto issueA = [&](int t) {
        __half* As = sm + (t % NSTAGE) * S_HALVES;
        const int k0 = t * BK;
        #pragma unroll
        for (int i = 0; i < 4; i++) {
            int f = tid + (i << 7);
            int r = f >> 2, ch = (f & 3) << 3;
            cp16(As + r * APITCH + ch, Ae + (size_t)(bm + r) * K + k0 + ch);
        }
    };
    auto issueB = [&](int t) {
        __half* Bs = sm + (t % NSTAGE) * S_HALVES + A_HALVES;
        const int k0 = t * BK;
        #pragma unroll
        for (int i = 0; i < 4; i++) {
            int f = tid + (i << 7);
            int r = f >> 4, ch = (f & 15) << 3;
            cp16(Bs + r * BPITCH + ch, Be + (size_t)(k0 + r) * N + bn + ch);
        }
        asm volatile("cp.async.commit_group;" ::: "memory");
    };

    // Prologue: stages 0..2 in flight.
    issueA(0); issueB(0);
    issueA(1); issueB(1);
    issueA(2); issueB(2);

    for (int t = 0; t < nk; t++) {
        asm volatile("cp.async.wait_group 2;" ::: "memory");
        __syncthreads();

        const __half* As = sm + (t % NSTAGE) * S_HALVES;
        const __half* Bs = As + A_HALVES;
        const uint32_t abase = smem_u32(As) + (((wm + rowsel) * APITCH) + col8) * 2;
        const uint32_t bbase = smem_u32(Bs) + ((rowsel * BPITCH) + wn + col8) * 2;

        if (t + 3 < nk) issueA(t + 3);   // spread fill: A-half before ks0

        #pragma unroll
        for (int ks = 0; ks < 2; ks++) {
            uint32_t a[4][4];
            #pragma unroll
            for (int i = 0; i < 4; i++) {
                uint32_t addr = abase + (i * 16 * APITCH + ks * 16) * 2;
                asm volatile(
                    "ldmatrix.sync.aligned.m8n8.x4.shared.b16 {%0,%1,%2,%3}, [%4];"
                    : "=r"(a[i][0]), "=r"(a[i][1]), "=r"(a[i][2]), "=r"(a[i][3])
                    : "r"(addr));
            }
            #pragma unroll
            for (int jp = 0; jp < 4; jp++) {
                uint32_t b0, b1, b2, b3;   // n-tiles 2jp (b0,b1) and 2jp+1 (b2,b3)
                uint32_t addr = bbase + (ks * 16 * BPITCH + jp * 16) * 2;
                asm volatile(
                    "ldmatrix.sync.aligned.m8n8.x4.trans.shared.b16 {%0,%1,%2,%3}, [%4];"
                    : "=r"(b0), "=r"(b1), "=r"(b2), "=r"(b3)
                    : "r"(addr));
                #pragma unroll
                for (int i = 0; i < 4; i++) {
                    asm volatile(
                        "mma.sync.aligned.m16n8k16.row.col.f32.f16.f16.f32 "
                        "{%0,%1,%2,%3}, {%4,%5,%6,%7}, {%8,%9}, {%0,%1,%2,%3};"
                        : "+f"(c[i][2*jp][0]), "+f"(c[i][2*jp][1]),
                          "+f"(c[i][2*jp][2]), "+f"(c[i][2*jp][3])
                        : "r"(a[i][0]), "r"(a[i][1]), "r"(a[i][2]), "r"(a[i][3]),
                          "r"(b0), "r"(b1));
                    asm volatile(
                        "mma.sync.aligned.m16n8k16.row.col.f32.f16.f16.f32 "
                        "{%0,%1,%2,%3}, {%4,%5,%6,%7}, {%8,%9}, {%0,%1,%2,%3};"
                        : "+f"(c[i][2*jp+1][0]), "+f"(c[i][2*jp+1][1]),
                          "+f"(c[i][2*jp+1][2]), "+f"(c[i][2*jp+1][3])
                        : "r"(a[i][0]), "r"(a[i][1]), "r"(a[i][2]), "r"(a[i][3]),
                          "r"(b2), "r"(b3));
                }
            }
            if (ks == 0 && t + 3 < nk) issueB(t + 3);   // B-half + commit after ks0
        }
    }

    // Epilogue
    #pragma unroll
    for (int i = 0; i < 4; i++) {
        int r0 = bm + wm + i * 16 + grp;
        #pragma unroll
        for (int j = 0; j < 8; j++) {
            int cn = bn + wn + j * 8 + 2 * qid;
            float bv0 = __ldg(be + cn), bv1 = __ldg(be + cn + 1);
            float v0 = c[i][j][0] + bv0;
            float v1 = c[i][j][1] + bv1;
            float v2 = c[i][j][2] + bv0;
            float v3 = c[i][j][3] + bv1;
            if (FIRST) {
                __half* Ce = (__half*)Cv + (size_t)e * M * N;
                __half2 h01 = __floats2half2_rn(fmaxf(v0, 0.f), fmaxf(v1, 0.f));
                __half2 h23 = __floats2half2_rn(fmaxf(v2, 0.f), fmaxf(v3, 0.f));
                *(__half2*)&Ce[(size_t)r0 * N + cn]       = h01;
                *(__half2*)&Ce[(size_t)(r0 + 8) * N + cn] = h23;
            } else {
                float* Ce = (float*)Cv + (size_t)e * M * N;
                st_cs_f2(&Ce[(size_t)r0 * N + cn],       v0, v1);
                st_cs_f2(&Ce[(size_t)(r0 + 8) * N + cn], v2, v3);
            }
        }
    }
}

extern "C" void kernel_launch(void* const* d_in, const int* in_sizes, int n_in,
                              void* d_out, int out_size)
{
    const float* x  = (const float*)d_in[0];   // [E, T, D]
    const float* w1 = (const float*)d_in[1];   // [E, D, H]
    const float* b1 = (const float*)d_in[2];   // [E, 1, H]
    const float* w2 = (const float*)d_in[3];   // [E, H, D]
    const float* b2 = (const float*)d_in[4];   // [E, 1, D]
    float* out = (float*)d_out;                // [E, T, D]

    __half *hid, *gx, *gw1, *gw2;
    cudaGetSymbolAddress((void**)&hid, g_hidden);
    cudaGetSymbolAddress((void**)&gx,  g_x);
    cudaGetSymbolAddress((void**)&gw1, g_w1);
    cudaGetSymbolAddress((void**)&gw2, g_w2);

    cudaFuncSetAttribute(ffn_gemm<true>,
                         cudaFuncAttributeMaxDynamicSharedMemorySize, DSMEM_BYTES);
    cudaFuncSetAttribute(ffn_gemm<false>,
                         cudaFuncAttributeMaxDynamicSharedMemorySize, DSMEM_BYTES);

    // Merged prepass: fp32 -> fp16 for x, w1, w2 in ONE launch (8 floats/thread/iter)
    const int nx8  = EXPERTS * TOK * DMODEL / 8;
    const int nw18 = EXPERTS * DMODEL * HID / 8;
    const int nw28 = EXPERTS * HID * DMODEL / 8;
    to_half3<<<1184, 256>>>((const float4*)x,  (uint4*)gx,  nx8,
                            (const float4*)w1, (uint4*)gw1, nw18,
                            (const float4*)w2, (uint4*)gw2, nw28);

    dim3 blk(128);
    // k1: BM=128, grid 32x16x8 = 4096
    ffn_gemm<true><<<dim3(HID / BN, TOK / BM, EXPERTS), blk, DSMEM_BYTES>>>(
        gx, gw1, b1, hid, TOK, HID, DMODEL);
    // k2: BM=128, grid 8x16x8 = 1024
    ffn_gemm<false><<<dim3(DMODEL / BN, TOK / BM, EXPERTS), blk, DSMEM_BYTES>>>(
        hid, gw2, b2, out, TOK, DMODEL, HID);
}

// round 17
// speedup vs baseline: 1.0624x; 1.0319x over previous
#include <cuda_runtime.h>
#include <cuda_fp16.h>
#include <cstdint>
#include <cstddef>

#define EXPERTS 8
#define TOK     2048
#define DMODEL  1024
#define HID     4096

// Static device scratch (no allocations allowed anywhere)
__device__ __half g_hidden[(size_t)EXPERTS * TOK * HID];   // fp16 hidden (written by k1)
__device__ __half g_x [(size_t)EXPERTS * TOK * DMODEL];    // fp16 x
__device__ __half g_w1[(size_t)EXPERTS * DMODEL * HID];    // fp16 w1
__device__ __half g_w2[(size_t)EXPERTS * HID * DMODEL];    // fp16 w2

// CTA tile 128x128, 128 threads (4 warps 2x2, 64x64 each), BK=64 fp16, 2-stage cp.async,
// 3 CTAs/SM. A via ldmatrix.x4 (pitch 144B = 9*16B odd -> conflict-free),
// B via ldmatrix.x4.trans (pitch 272B = 17*16B odd -> conflict-free).
// Halved barrier count vs BK=32 (16/64 iters for k1/k2).
#define BM 128
#define BN 128
#define BK 64
#define APITCH 72      // halves (144 B/row)
#define BPITCH 136     // halves (272 B/row)
#define A_HALVES (BM * APITCH)            // 9216
#define B_HALVES (BK * BPITCH)            // 8704
#define S_HALVES (A_HALVES + B_HALVES)    // 17920 (35840 B/stage)
#define NSTAGE 2
#define DSMEM_BYTES (NSTAGE * S_HALVES * 2)   // 71680 B -> 3 CTAs/SM (215KB)

static __device__ __forceinline__ uint32_t smem_u32(const void* p) {
    uint32_t a;
    asm("{ .reg .u64 t; cvta.to.shared.u64 t, %1; cvt.u32.u64 %0, t; }" : "=r"(a) : "l"(p));
    return a;
}
static __device__ __forceinline__ void cp16(void* d, const void* s) {
    asm volatile("cp.async.cg.shared.global [%0], [%1], 16;" :: "r"(smem_u32(d)), "l"(s));
}
static __device__ __forceinline__ uint32_t h2u(__half2 h) {
    uint32_t u;
    asm("mov.b32 %0, %1;" : "=r"(u) : "r"(*(uint32_t*)&h));
    return u;
}
// streaming (evict-first) float2 store — for outputs that are never re-read
static __device__ __forceinline__ void st_cs_f2(float* p, float x, float y) {
    asm volatile("st.global.cs.v2.f32 [%0], {%1, %2};" :: "l"(p), "f"(x), "f"(y) : "memory");
}

// Merged fp32 -> fp16 prepass over three arrays, 8 floats/thread/iter
__global__ void to_half3(const float4* __restrict__ inx,  uint4* __restrict__ outx,  int nx8,
                         const float4* __restrict__ inw1, uint4* __restrict__ outw1, int nw18,
                         const float4* __restrict__ inw2, uint4* __restrict__ outw2, int nw28)
{
    const int total = nx8 + nw18 + nw28;
    for (int i = blockIdx.x * blockDim.x + threadIdx.x; i < total; i += gridDim.x * blockDim.x) {
        const float4* in;
        uint4* out;
        int k;
        if (i < nx8)             { in = inx;  out = outx;  k = i; }
        else if (i < nx8 + nw18) { in = inw1; out = outw1; k = i - nx8; }
        else                     { in = inw2; out = outw2; k = i - nx8 - nw18; }
        float4 v0 = in[2 * k];
        float4 v1 = in[2 * k + 1];
        __half2 h0 = __floats2half2_rn(v0.x, v0.y);
        __half2 h1 = __floats2half2_rn(v0.z, v0.w);
        __half2 h2 = __floats2half2_rn(v1.x, v1.y);
        __half2 h3 = __floats2half2_rn(v1.z, v1.w);
        uint4 o;
        o.x = h2u(h0); o.y = h2u(h1); o.z = h2u(h2); o.w = h2u(h3);
        out[k] = o;
    }
}

// C = A[M,K]*B[K,N] + bias.  A,B fp16 row-major.  FIRST: ReLU + fp16 store (hidden);
// else: fp32 streaming store. Batched over blockIdx.z.
template <bool FIRST>
__global__ __launch_bounds__(128, 3)
void ffn_gemm(const __half* __restrict__ A, const __half* __restrict__ B,
              const float* __restrict__ bias, void* __restrict__ Cv,
              int M, int N, int K)
{
    extern __shared__ __align__(16) __half sm[];

    const int e = blockIdx.z;
    const __half* Ae = A + (size_t)e * M * K;
    const __half* Be = B + (size_t)e * K * N;
    const float*  be = bias + (size_t)e * N;

    const int bm = blockIdx.y * BM;
    const int bn = blockIdx.x * BN;

    const int tid  = threadIdx.x;
    const int warp = tid >> 5;
    const int lane = tid & 31;
    const int wm   = (warp >> 1) * 64;
    const int wn   = (warp & 1) * 64;
    const int grp  = lane >> 2;
    const int qid  = lane & 3;
    const int rowsel = ((lane >> 3) & 1) * 8 + (lane & 7);  // row within 16
    const int col8   = (lane >> 4) * 8;                     // 8-half column block

    float c[4][8][4];
    #pragma unroll
    for (int i = 0; i < 4; i++)
        #pragma unroll
        for (int j = 0; j < 8; j++)
            #pragma unroll
            for (int r = 0; r < 4; r++) c[i][j][r] = 0.f;

    const int nk = K / BK;

    // cp.async halves: A (128 rows x 8 x 16B = 1024 chunks), B (64 rows x 16 x 16B = 1024);
    // 8 + 8 chunks per thread, one commit per k-tile.
    auto issueA = [&](int t) {
        __half* As = sm + (t % NSTAGE) * S_HALVES;
        const int k0 = t * BK;
        #pragma unroll
        for (int i = 0; i < 8; i++) {
            int f = tid + (i << 7);
            int r = f >> 3, ch = (f & 7) << 3;
            cp16(As + r * APITCH + ch, Ae + (size_t)(bm + r) * K + k0 + ch);
        }
    };
    auto issueB = [&](int t) {
        __half* Bs = sm + (t % NSTAGE) * S_HALVES + A_HALVES;
        const int k0 = t * BK;
        #pragma unroll
        for (int i = 0; i < 8; i++) {
            int f = tid + (i << 7);
            int r = f >> 4, ch = (f & 15) << 3;
            cp16(Bs + r * BPITCH + ch, Be + (size_t)(k0 + r) * N + bn + ch);
        }
        asm volatile("cp.async.commit_group;" ::: "memory");
    };

    // Prologue: stage 0 in flight.
    issueA(0); issueB(0);

    for (int t = 0; t < nk; t++) {
        asm volatile("cp.async.wait_group 0;" ::: "memory");   // stage t landed
        __syncthreads();                                        // all warps done with stage t-1

        const __half* As = sm + (t % NSTAGE) * S_HALVES;
        const __half* Bs = As + A_HALVES;
        const uint32_t abase = smem_u32(As) + (((wm + rowsel) * APITCH) + col8) * 2;
        const uint32_t bbase = smem_u32(Bs) + ((rowsel * BPITCH) + wn + col8) * 2;

        #pragma unroll
        for (int ks = 0; ks < 4; ks++) {
            uint32_t a[4][4];
            #pragma unroll
            for (int i = 0; i < 4; i++) {
                uint32_t addr = abase + (i * 16 * APITCH + ks * 16) * 2;
                asm volatile(
                    "ldmatrix.sync.aligned.m8n8.x4.shared.b16 {%0,%1,%2,%3}, [%4];"
                    : "=r"(a[i][0]), "=r"(a[i][1]), "=r"(a[i][2]), "=r"(a[i][3])
                    : "r"(addr));
            }
            #pragma unroll
            for (int jp = 0; jp < 4; jp++) {
                uint32_t b0, b1, b2, b3;   // n-tiles 2jp (b0,b1) and 2jp+1 (b2,b3)
                uint32_t addr = bbase + (ks * 16 * BPITCH + jp * 16) * 2;
                asm volatile(
                    "ldmatrix.sync.aligned.m8n8.x4.trans.shared.b16 {%0,%1,%2,%3}, [%4];"
                    : "=r"(b0), "=r"(b1), "=r"(b2), "=r"(b3)
                    : "r"(addr));
                #pragma unroll
                for (int i = 0; i < 4; i++) {
                    asm volatile(
                        "mma.sync.aligned.m16n8k16.row.col.f32.f16.f16.f32 "
                        "{%0,%1,%2,%3}, {%4,%5,%6,%7}, {%8,%9}, {%0,%1,%2,%3};"
                        : "+f"(c[i][2*jp][0]), "+f"(c[i][2*jp][1]),
                          "+f"(c[i][2*jp][2]), "+f"(c[i][2*jp][3])
                        : "r"(a[i][0]), "r"(a[i][1]), "r"(a[i][2]), "r"(a[i][3]),
                          "r"(b0), "r"(b1));
                    asm volatile(
                        "mma.sync.aligned.m16n8k16.row.col.f32.f16.f16.f32 "
                        "{%0,%1,%2,%3}, {%4,%5,%6,%7}, {%8,%9}, {%0,%1,%2,%3};"
                        : "+f"(c[i][2*jp+1][0]), "+f"(c[i][2*jp+1][1]),
                          "+f"(c[i][2*jp+1][2]), "+f"(c[i][2*jp+1][3])
                        : "r"(a[i][0]), "r"(a[i][1]), "r"(a[i][2]), "r"(a[i][3]),
                          "r"(b2), "r"(b3));
                }
            }
            // Spread next-stage fill across the compute window.
            if (ks == 0 && t + 1 < nk) issueA(t + 1);
            if (ks == 1 && t + 1 < nk) issueB(t + 1);   // commit after ks1
        }
    }

    // Epilogue
    #pragma unroll
    for (int i = 0; i < 4; i++) {
        int r0 = bm + wm + i * 16 + grp;
        #pragma unroll
        for (int j = 0; j < 8; j++) {
            int cn = bn + wn + j * 8 + 2 * qid;
            float bv0 = __ldg(be + cn), bv1 = __ldg(be + cn + 1);
            float v0 = c[i][j][0] + bv0;
            float v1 = c[i][j][1] + bv1;
            float v2 = c[i][j][2] + bv0;
            float v3 = c[i][j][3] + bv1;
            if (FIRST) {
                __half* Ce = (__half*)Cv + (size_t)e * M * N;
                __half2 h01 = __floats2half2_rn(fmaxf(v0, 0.f), fmaxf(v1, 0.f));
                __half2 h23 = __floats2half2_rn(fmaxf(v2, 0.f), fmaxf(v3, 0.f));
                *(__half2*)&Ce[(size_t)r0 * N + cn]       = h01;
                *(__half2*)&Ce[(size_t)(r0 + 8) * N + cn] = h23;
            } else {
                float* Ce = (float*)Cv + (size_t)e * M * N;
                st_cs_f2(&Ce[(size_t)r0 * N + cn],       v0, v1);
                st_cs_f2(&Ce[(size_t)(r0 + 8) * N + cn], v2, v3);
            }
        }
    }
}

extern "C" void kernel_launch(void* const* d_in, const int* in_sizes, int n_in,
                              void* d_out, int out_size)
{
    const float* x  = (const float*)d_in[0];   // [E, T, D]
    const float* w1 = (const float*)d_in[1];   // [E, D, H]
    const float* b1 = (const float*)d_in[2];   // [E, 1, H]
    const float* w2 = (const float*)d_in[3];   // [E, H, D]
    const float* b2 = (const float*)d_in[4];   // [E, 1, D]
    float* out = (float*)d_out;                // [E, T, D]

    __half *hid, *gx, *gw1, *gw2;
    cudaGetSymbolAddress((void**)&hid, g_hidden);
    cudaGetSymbolAddress((void**)&gx,  g_x);
    cudaGetSymbolAddress((void**)&gw1, g_w1);
    cudaGetSymbolAddress((void**)&gw2, g_w2);

    cudaFuncSetAttribute(ffn_gemm<true>,
                         cudaFuncAttributeMaxDynamicSharedMemorySize, DSMEM_BYTES);
    cudaFuncSetAttribute(ffn_gemm<false>,
                         cudaFuncAttributeMaxDynamicSharedMemorySize, DSMEM_BYTES);

    // Merged prepass: fp32 -> fp16 for x, w1, w2 in ONE launch (8 floats/thread/iter)
    const int nx8  = EXPERTS * TOK * DMODEL / 8;
    const int nw18 = EXPERTS * DMODEL * HID / 8;
    const int nw28 = EXPERTS * HID * DMODEL / 8;
    to_half3<<<1184, 256>>>((const float4*)x,  (uint4*)gx,  nx8,
                            (const float4*)w1, (uint4*)gw1, nw18,
                            (const float4*)w2, (uint4*)gw2, nw28);

    dim3 blk(128);
    // k1: BM=128, grid 32x16x8 = 4096, nk=16
    ffn_gemm<true><<<dim3(HID / BN, TOK / BM, EXPERTS), blk, DSMEM_BYTES>>>(
        gx, gw1, b1, hid, TOK, HID, DMODEL);
    // k2: BM=128, grid 8x16x8 = 1024, nk=64
    ffn_gemm<false><<<dim3(DMODEL / BN, TOK / BM, EXPERTS), blk, DSMEM_BYTES>>>(
        hid, gw2, b2, out, TOK, DMODEL, HID);
}